// round 17
// baseline (speedup 1.0000x reference)
#include <cuda_runtime.h>
#include <cuda_fp16.h>
#include <math.h>
#include <cstdint>

#define NN   50000
#define NE   800000
#define IND  128
#define HID  256
#define OUTD 40
#define NB   ((NN + 255) / 256)   // 196 scan blocks
#define ROWS_H1 25088             // 196 mega tiles; h2 = 195 tiles

// ---------------- scratch ----------------------------------------------------
__device__ int   g_counts[NN];          // zero at load; re-zeroed by agg2 tail
__device__ int   g_offsets[NN + 1];
__device__ int   g_rank[NE];
__device__ int   g_esrc[NE];
__device__ float g_invc[NN];
__device__ int   g_bsum[NB];
__device__ int   g_done1 = 0;
__device__ int   g_done2 = 0;
__device__ __align__(16) __half g_a_hi[(size_t)NN * HID];  // [agg|x] fp16
__device__ __align__(16) __half g_w1hi[(size_t)HID * HID]; // W1^T fp16 [n][k]
__device__ __align__(16) __half g_w2hi[(size_t)80 * HID];  // W2^T fp16 [80][256]
__device__ __align__(16) __half g_p[(size_t)NN * OUTD];    // p fp16 [NN][40]
__device__ __align__(16) float g_r[(size_t)NN * OUTD];

// ---------------- helpers ----------------------------------------------------
__device__ __forceinline__ uint32_t smem_u32(const void* p) {
    uint32_t a;
    asm("{ .reg .u64 t; cvta.to.shared.u64 t, %1; cvt.u32.u64 %0, t; }"
        : "=r"(a) : "l"(p));
    return a;
}

#define SW128(o) ((o) ^ (((o) >> 3) & 0x70))

#define LDSM4(R, ADDR)                                                           \
    asm volatile("ldmatrix.sync.aligned.m8n8.x4.shared.b16 {%0,%1,%2,%3}, [%4];" \
        : "=r"((R)[0]), "=r"((R)[1]), "=r"((R)[2]), "=r"((R)[3]) : "r"(ADDR))

__device__ __forceinline__ void mma16816(float* c, const uint32_t* a,
                                         uint32_t b0, uint32_t b1) {
    asm volatile(
        "mma.sync.aligned.m16n8k16.row.col.f32.f16.f16.f32 "
        "{%0,%1,%2,%3}, {%4,%5,%6,%7}, {%8,%9}, {%0,%1,%2,%3};"
        : "+f"(c[0]), "+f"(c[1]), "+f"(c[2]), "+f"(c[3])
        : "r"(a[0]), "r"(a[1]), "r"(a[2]), "r"(a[3]), "r"(b0), "r"(b1));
}

__device__ __forceinline__ void cp_async16(uint32_t dst, const void* src, int srcsz) {
    asm volatile("cp.async.cg.shared.global [%0], [%1], 16, %2;"
                 :: "r"(dst), "l"(src), "r"(srcsz) : "memory");
}
#define CP_COMMIT() asm volatile("cp.async.commit_group;" ::: "memory")
#define CP_WAIT1()  asm volatile("cp.async.wait_group 1;" ::: "memory")
#define CP_WAIT0()  asm volatile("cp.async.wait_group 0;" ::: "memory")

// per-block edge dtype detection (odd words all zero over 32 samples <=> int64)
__device__ __forceinline__ int detect_is64(const int* __restrict__ ei32) {
    __shared__ int s_is64;
    if (threadIdx.x < 32) {
        int v = ei32[2 * threadIdx.x + 1];
        unsigned b = __ballot_sync(0xffffffffu, v != 0);
        if (threadIdx.x == 0) s_is64 = (b == 0) ? 1 : 0;
    }
    __syncthreads();
    return s_is64;
}

__device__ __forceinline__ int edge_at(const void* ei, int idx, int is64) {
    if (is64) return (int)((const long long*)ei)[idx];
    return ((const int*)ei)[idx];
}

// ---------------- k_count_prep: edge count+rank ∥ W1/W2/x fp16 prep ----------
#define CPB_COUNT 3125
#define CPB_W1    (CPB_COUNT + 256)
#define CPB_W2    (CPB_W1 + 80)
#define CPB_X     (CPB_W2 + 6250)

__global__ void k_count_prep(const void* __restrict__ ei,
                             const float* __restrict__ W1l, const float* __restrict__ W1r,
                             const float* __restrict__ W2l, const float* __restrict__ W2r,
                             const float* __restrict__ x) {
    int b = blockIdx.x;
    int tid = threadIdx.x;
    if (b < CPB_COUNT) {
        int is64 = detect_is64((const int*)ei);
        int e = b * 256 + tid;
        if (e < NE) {
            int d = edge_at(ei, NE + e, is64);
            g_rank[e] = atomicAdd(&g_counts[d], 1);
        }
    } else if (b < CPB_W1) {
        int idx = (b - CPB_COUNT) * 256 + tid;
        int n = idx >> 8, k = idx & 255;
        float w = (k < 128) ? W1l[(size_t)k * 256 + n]
                            : W1r[(size_t)(k - 128) * 256 + n];
        g_w1hi[(size_t)n * 256 + k] = __float2half_rn(w);
    } else if (b < CPB_W2) {
        int idx = (b - CPB_W1) * 256 + tid;
        int n = idx >> 8, k = idx & 255;
        float w = (n < 40) ? W2l[(size_t)k * 40 + n]
                           : W2r[(size_t)k * 40 + (n - 40)];
        g_w2hi[(size_t)n * 256 + k] = __float2half_rn(w);
    } else {
        int idx = (b - CPB_W2) * 256 + tid;
        if (idx >= NN * 32) return;
        int row = idx >> 5, c4 = idx & 31;
        float4 v = ((const float4*)x)[(size_t)row * 32 + c4];
        __half2 h0 = __floats2half2_rn(v.x, v.y);
        __half2 h1 = __floats2half2_rn(v.z, v.w);
        uint2 hi;
        hi.x = *(uint32_t*)&h0;
        hi.y = *(uint32_t*)&h1;
        *(uint2*)&g_a_hi[(size_t)row * 256 + 128 + c4 * 4] = hi;
    }
}

// ---------------- k_scan: fused hierarchical scan ----------------------------
__device__ __forceinline__ int block_excl_scan(int c, int t) {
    int lane = t & 31, w = t >> 5;
    int v = c;
#pragma unroll
    for (int off = 1; off < 32; off <<= 1) {
        int n = __shfl_up_sync(0xffffffffu, v, off);
        if (lane >= off) v += n;
    }
    __shared__ int ws[8];
    if (lane == 31) ws[w] = v;
    __syncthreads();
    if (w == 0 && lane < 8) {
        int s = ws[lane];
#pragma unroll
        for (int off = 1; off < 8; off <<= 1) {
            int n = __shfl_up_sync(0x000000ffu, s, off);
            if (lane >= off) s += n;
        }
        ws[lane] = s;
    }
    __syncthreads();
    return v - c + (w > 0 ? ws[w - 1] : 0);
}

__global__ void k_scan() {
    int b = blockIdx.x, tid = threadIdx.x;
    int i = b * 256 + tid;
    int c = (i < NN) ? g_counts[i] : 0;
    int e = block_excl_scan(c, tid);

    if (tid == 255) {
        g_bsum[b] = e + c;
        __threadfence();
        atomicAdd(&g_done1, 1);
    }
    if (tid == 0) {
        while (*(volatile int*)&g_done1 < NB) {}
    }
    __syncthreads();
    __threadfence();

    int v = (tid < b) ? g_bsum[tid] : 0;
    int lane = tid & 31, w = tid >> 5;
#pragma unroll
    for (int off = 16; off; off >>= 1) v += __shfl_xor_sync(0xffffffffu, v, off);
    __shared__ int rs[8];
    if (lane == 0) rs[w] = v;
    __syncthreads();
    __shared__ int pre;
    if (tid == 0) {
        int s = 0;
#pragma unroll
        for (int k = 0; k < 8; k++) s += rs[k];
        pre = s;
    }
    __syncthreads();

    if (i < NN) {
        g_offsets[i] = pre + e;
        g_invc[i]    = 1.0f / (float)(c > 1 ? c : 1);
    }
    if (b == NB - 1 && tid == 255) g_offsets[NN] = NE;

    if (tid == 0) {
        int t2 = atomicAdd(&g_done2, 1);
        if (t2 == NB - 1) { g_done1 = 0; g_done2 = 0; }
    }
}

// ---------------- k_scatter: atomic-free via precomputed rank ----------------
__global__ void k_scatter(const void* __restrict__ ei) {
    int is64 = detect_is64((const int*)ei);
    int e = blockIdx.x * blockDim.x + threadIdx.x;
    if (e < NE) {
        int s = edge_at(ei, e, is64);
        int d = edge_at(ei, NE + e, is64);
        g_esrc[g_offsets[d] + g_rank[e]] = s;
    }
}

// ---------------- layer-1 aggregation (node range [n0,n1)) -------------------
__global__ void k_agg1(int n0, int n1) {
    int warp = n0 + ((blockIdx.x * blockDim.x + threadIdx.x) >> 5);
    if (warp >= n1) return;
    int lane = threadIdx.x & 31;
    int beg = g_offsets[warp], end = g_offsets[warp + 1];
    float4 acc = make_float4(0.f, 0.f, 0.f, 0.f);
    size_t lo = 128 + lane * 4;
    int e = beg;
    for (; e + 3 < end; e += 4) {
        int s0 = g_esrc[e];
        int s1 = g_esrc[e + 1];
        int s2 = g_esrc[e + 2];
        int s3 = g_esrc[e + 3];
        uint2 u0 = *(const uint2*)&g_a_hi[(size_t)s0 * 256 + lo];
        uint2 u1 = *(const uint2*)&g_a_hi[(size_t)s1 * 256 + lo];
        uint2 u2 = *(const uint2*)&g_a_hi[(size_t)s2 * 256 + lo];
        uint2 u3 = *(const uint2*)&g_a_hi[(size_t)s3 * 256 + lo];
        __half2 a01 = __hadd2(*(__half2*)&u0.x, *(__half2*)&u1.x);
        __half2 b01 = __hadd2(*(__half2*)&u0.y, *(__half2*)&u1.y);
        __half2 a23 = __hadd2(*(__half2*)&u2.x, *(__half2*)&u3.x);
        __half2 b23 = __hadd2(*(__half2*)&u2.y, *(__half2*)&u3.y);
        float2 f0 = __half22float2(__hadd2(a01, a23));
        float2 f1 = __half22float2(__hadd2(b01, b23));
        acc.x += f0.x; acc.y += f0.y; acc.z += f1.x; acc.w += f1.y;
    }
    for (; e < end; e++) {
        int s0 = g_esrc[e];
        uint2 u0 = *(const uint2*)&g_a_hi[(size_t)s0 * 256 + lo];
        float2 f0 = __half22float2(*(__half2*)&u0.x);
        float2 f1 = __half22float2(*(__half2*)&u0.y);
        acc.x += f0.x; acc.y += f0.y; acc.z += f1.x; acc.w += f1.y;
    }
    float iv = g_invc[warp];
    __half2 h0 = __floats2half2_rn(acc.x * iv, acc.y * iv);
    __half2 h1 = __floats2half2_rn(acc.z * iv, acc.w * iv);
    uint2 hi;
    hi.x = *(uint32_t*)&h0;
    hi.y = *(uint32_t*)&h1;
    *(uint2*)&g_a_hi[(size_t)warp * 256 + lane * 4] = hi;
}

// ---------------- MEGA kernel: gemm1 (BN=256) + gemm2 fused, pure fp16 -------
#define MH_HI   0
#define MB_A_HI 0
#define MB_B_HI 16384
#define MSTG    65536
#define MBUFSZ  49152
#define MB2_HI  65536
#define MB2_CH  11264          // 88 rows * 128B per chunk
#define DYN_SMEMM 163840

__global__ void __launch_bounds__(512, 1) k_mega(const float* __restrict__ b1,
                                                 const float* __restrict__ b2,
                                                 int tile0) {
    extern __shared__ char dsm[];
    int tid = threadIdx.x;
    int wid = tid >> 5;          // 0..15
    int lane = tid & 31;
    int bm = (blockIdx.x + tile0) * 128;
    uint32_t dynb = smem_u32(dsm);

    int warp_m = (wid & 3) * 32;
    int warp_n = (wid >> 2) * 64;

    uint32_t offA[2][4], offB[4][4];
    {
        int mat = lane >> 3, rr = lane & 7;
#pragma unroll
        for (int i = 0; i < 2; i++)
#pragma unroll
            for (int j = 0; j < 4; j++) {
                int row = warp_m + i * 16 + ((mat & 1) << 3) + rr;
                int kb  = j * 16 + ((mat >> 1) << 3);
                offA[i][j] = SW128(row * 128 + kb * 2);
            }
#pragma unroll
        for (int q = 0; q < 4; q++)
#pragma unroll
            for (int j = 0; j < 4; j++) {
                int n  = warp_n + q * 16 + ((mat & 2) << 2) + rr;
                int kb = j * 16 + ((mat & 1) << 3);
                offB[q][j] = SW128(n * 128 + kb * 2);
            }
    }

    float acc[2][8][4];
#pragma unroll
    for (int i = 0; i < 2; i++)
#pragma unroll
        for (int jn = 0; jn < 8; jn++)
#pragma unroll
            for (int t = 0; t < 4; t++) acc[i][jn][t] = 0.f;

#define STAGEM(K0, BUFO) do {                                                      \
    _Pragma("unroll")                                                              \
    for (int it = 0; it < 2; it++) {                                               \
        int idx = tid + it * 512;                                                  \
        int row = idx >> 3, seg = idx & 7;                                         \
        int grow = bm + row;                                                       \
        int cl = grow < NN ? grow : (NN - 1);                                      \
        int sz = grow < NN ? 16 : 0;                                               \
        size_t boff = ((size_t)cl * 256 + (K0) + seg * 8) * 2;                     \
        int so = SW128(row * 128 + seg * 16);                                      \
        cp_async16(dynb + (BUFO) + MB_A_HI + so, (const char*)g_a_hi + boff, sz);  \
    }                                                                              \
    _Pragma("unroll")                                                              \
    for (int it = 0; it < 4; it++) {                                               \
        int idx = tid + it * 512;                                                  \
        int row = idx >> 3, seg = idx & 7;                                         \
        size_t boff = ((size_t)row * 256 + (K0) + seg * 8) * 2;                    \
        int so = SW128(row * 128 + seg * 16);                                      \
        cp_async16(dynb + (BUFO) + MB_B_HI + so, (const char*)g_w1hi + boff, 16);  \
    }                                                                              \
} while (0)

    STAGEM(0, MSTG);            CP_COMMIT();
    STAGEM(64, MSTG + MBUFSZ);  CP_COMMIT();

    for (int kc = 0; kc < 4; kc++) {
        uint32_t bufo = MSTG + ((kc & 1) ? MBUFSZ : 0);
        CP_WAIT1();
        __syncthreads();
#pragma unroll
        for (int j = 0; j < 4; j++) {
            uint32_t ah[2][4];
#pragma unroll
            for (int i = 0; i < 2; i++)
                LDSM4(ah[i], dynb + bufo + MB_A_HI + offA[i][j]);
#pragma unroll
            for (int q = 0; q < 4; q++) {
                uint32_t bh[4];
                LDSM4(bh, dynb + bufo + MB_B_HI + offB[q][j]);
#pragma unroll
                for (int i = 0; i < 2; i++)
#pragma unroll
                    for (int hsel = 0; hsel < 2; hsel++) {
                        int jn = q * 2 + hsel;
                        mma16816(acc[i][jn], ah[i], bh[hsel * 2], bh[hsel * 2 + 1]);
                    }
            }
        }
        __syncthreads();
        if (kc < 2) STAGEM((kc + 2) * 64, bufo);
        CP_COMMIT();
    }
#undef STAGEM

    // ===== phase 1 epilogue: h -> smem fp16, stage W2 into dead staging area =
    {
        if (tid < 256) {
            int kcz = tid >> 6, q4 = tid & 63;
            *(uint4*)(dsm + MB2_HI + kcz * MB2_CH + 80 * 128 + q4 * 16) =
                make_uint4(0, 0, 0, 0);
        }
#pragma unroll
        for (int it = 0; it < 5; it++) {
            int idx = tid + it * 512;
            int kc2 = idx / 640;
            int rr2 = idx - kc2 * 640;
            int row = rr2 >> 3, seg = rr2 & 7;
            const char* src = (const char*)g_w2hi
                              + ((size_t)row * 256 + kc2 * 64 + seg * 8) * 2;
            uint32_t dst = dynb + MB2_HI + kc2 * MB2_CH
                           + SW128(row * 128 + seg * 16);
            cp_async16(dst, src, 16);
        }
        CP_COMMIT();
    }

    {
        int r0l = warp_m + (lane >> 2);
        int c0l = warp_n + 2 * (lane & 3);
#pragma unroll
        for (int i = 0; i < 2; i++) {
#pragma unroll
            for (int jn = 0; jn < 8; jn++) {
                int col = c0l + jn * 8;
                int kc = col >> 6, kin = col & 63;
                float bx = b1[col], by = b1[col + 1];
                {
                    int r = r0l + i * 16;
                    float vx = acc[i][jn][0] + bx; vx = vx > 0.f ? vx : 0.f;
                    float vy = acc[i][jn][1] + by; vy = vy > 0.f ? vy : 0.f;
                    __half2 h = __floats2half2_rn(vx, vy);
                    int so = kc * 16384 + SW128(r * 128 + kin * 2);
                    *(uint32_t*)(dsm + MH_HI + so) = *(uint32_t*)&h;
                }
                {
                    int r = r0l + i * 16 + 8;
                    float vx = acc[i][jn][2] + bx; vx = vx > 0.f ? vx : 0.f;
                    float vy = acc[i][jn][3] + by; vy = vy > 0.f ? vy : 0.f;
                    __half2 h = __floats2half2_rn(vx, vy);
                    int so = kc * 16384 + SW128(r * 128 + kin * 2);
                    *(uint32_t*)(dsm + MH_HI + so) = *(uint32_t*)&h;
                }
            }
        }
    }
    CP_WAIT0();
    __syncthreads();

    // ===== phase 2: gemm2 from smem. warp tile 16x40, 8x2 warps ==============
    int warp_m2 = (wid & 7) * 16;
    int warp_n2 = (wid >> 3) * 40;

    uint32_t offA2[4], offB2[3][4];
    {
        int mat = lane >> 3, rr = lane & 7;
#pragma unroll
        for (int jj = 0; jj < 4; jj++) {
            int row = warp_m2 + ((mat & 1) << 3) + rr;
            int kb  = jj * 16 + ((mat >> 1) << 3);
            offA2[jj] = SW128(row * 128 + kb * 2);
        }
#pragma unroll
        for (int q = 0; q < 3; q++)
#pragma unroll
            for (int jj = 0; jj < 4; jj++) {
                int n  = warp_n2 + q * 16 + ((mat & 2) << 2) + rr;
                int kb = jj * 16 + ((mat & 1) << 3);
                offB2[q][jj] = SW128(n * 128 + kb * 2);
            }
    }

    float acc2[5][4];
#pragma unroll
    for (int jn = 0; jn < 5; jn++)
#pragma unroll
        for (int t = 0; t < 4; t++) acc2[jn][t] = 0.f;

#pragma unroll
    for (int j = 0; j < 16; j++) {
        int kc = j >> 2, jj = j & 3;
        uint32_t ah[4];
        LDSM4(ah, dynb + MH_HI + kc * 16384 + offA2[jj]);
#pragma unroll
        for (int q = 0; q < 3; q++) {
            uint32_t bh[4];
            LDSM4(bh, dynb + MB2_HI + kc * MB2_CH + offB2[q][jj]);
#pragma unroll
            for (int h2 = 0; h2 < 2; h2++) {
                int jn = q * 2 + h2;
                if (jn < 5)
                    mma16816(acc2[jn], ah, bh[h2 * 2], bh[h2 * 2 + 1]);
            }
        }
    }

    // epilogue: cols<40 -> p (fp16, no bias), cols>=40 -> r (fp32, +b2)
    int r0 = bm + warp_m2 + (lane >> 2);
    int c0 = warp_n2 + 2 * (lane & 3);
#pragma unroll
    for (int jn = 0; jn < 5; jn++) {
        int col = c0 + jn * 8;
#pragma unroll
        for (int half = 0; half < 2; half++) {
            int row = r0 + half * 8;
            if (row < NN) {
                float vx = acc2[jn][half * 2 + 0];
                float vy = acc2[jn][half * 2 + 1];
                if (col < 40) {
                    __half2 hp = __floats2half2_rn(vx, vy);
                    *(__half2*)&g_p[(size_t)row * 40 + col] = hp;
                } else {
                    float2 v = make_float2(vx + b2[col - 40], vy + b2[col - 39]);
                    *(float2*)&g_r[(size_t)row * 40 + (col - 40)] = v;
                }
            }
        }
    }
}

// ---------------- layer-2 aggregation + log_softmax + counts reset -----------
__global__ void k_agg2_lsm(float* __restrict__ out) {
    if (blockIdx.x < NB) {
        int ci = blockIdx.x * 256 + threadIdx.x;
        if (ci < NN) g_counts[ci] = 0;
    }

    int warp = (blockIdx.x * blockDim.x + threadIdx.x) >> 5;
    if (warp >= NN) return;
    int lane = threadIdx.x & 31;
    int beg = g_offsets[warp], end = g_offsets[warp + 1];
    bool h1 = lane < 8;
    float a0 = 0.f, a1 = 0.f;
    int e = beg;
    for (; e + 1 < end; e += 2) {
        int s0 = g_esrc[e];
        int s1 = g_esrc[e + 1];
        const __half* p0 = g_p + (size_t)s0 * 40;
        const __half* p1 = g_p + (size_t)s1 * 40;
        float v00 = __half2float(p0[lane]);
        float v01 = __half2float(p1[lane]);
        a0 += v00 + v01;
        if (h1) {
            float v10 = __half2float(p0[32 + lane]);
            float v11 = __half2float(p1[32 + lane]);
            a1 += v10 + v11;
        }
    }
    if (e < end) {
        int s0 = g_esrc[e];
        const __half* ps = g_p + (size_t)s0 * 40;
        a0 += __half2float(ps[lane]);
        if (h1) a1 += __half2float(ps[32 + lane]);
    }
    float iv = g_invc[warp];
    float v0 = a0 * iv + g_r[(size_t)warp * 40 + lane];
    float v1 = h1 ? (a1 * iv + g_r[(size_t)warp * 40 + 32 + lane]) : -3.0e38f;

    float m = fmaxf(v0, v1);
#pragma unroll
    for (int off = 16; off; off >>= 1)
        m = fmaxf(m, __shfl_xor_sync(0xffffffffu, m, off));
    float ssum = expf(v0 - m) + (h1 ? expf(v1 - m) : 0.f);
#pragma unroll
    for (int off = 16; off; off >>= 1)
        ssum += __shfl_xor_sync(0xffffffffu, ssum, off);
    float lse = m + logf(ssum);

    out[(size_t)warp * 40 + lane] = v0 - lse;
    if (h1) out[(size_t)warp * 40 + 32 + lane] = v1 - lse;
}

// ---------------- launch -----------------------------------------------------
extern "C" void kernel_launch(void* const* d_in, const int* in_sizes, int n_in,
                              void* d_out, int out_size) {
    const float* x   = (const float*)d_in[0];
    const void*  ei  = d_in[1];
    const float* W1l = (const float*)d_in[2];
    const float* W1r = (const float*)d_in[3];
    const float* b1  = (const float*)d_in[4];
    const float* W2l = (const float*)d_in[5];
    const float* W2r = (const float*)d_in[6];
    const float* b2  = (const float*)d_in[7];
    float* out = (float*)d_out;

    static cudaStream_t s2 = nullptr;
    static cudaEvent_t evA = nullptr, evB = nullptr;
    if (s2 == nullptr) {
        cudaStreamCreateWithFlags(&s2, cudaStreamNonBlocking);
        cudaEventCreateWithFlags(&evA, cudaEventDisableTiming);
        cudaEventCreateWithFlags(&evB, cudaEventDisableTiming);
        cudaFuncSetAttribute(k_mega, cudaFuncAttributeMaxDynamicSharedMemorySize,
                             DYN_SMEMM);
    }

    k_count_prep<<<CPB_X, 256>>>(ei, W1l, W1r, W2l, W2r, x);
    k_scan<<<NB, 256>>>();
    k_scatter<<<(NE + 255) / 256, 256>>>(ei);

    // agg1 first half on main stream
    k_agg1<<<(ROWS_H1 + 7) / 8, 256>>>(0, ROWS_H1);
    cudaEventRecord(evA, 0);

    // agg1 second half on side stream (concurrent with mega_h1)
    cudaStreamWaitEvent(s2, evA, 0);
    k_agg1<<<((NN - ROWS_H1) + 7) / 8, 256, 0, s2>>>(ROWS_H1, NN);
    cudaEventRecord(evB, s2);

    // mega first half (rows [0, 25088) -> tiles 0..195)
    k_mega<<<ROWS_H1 / 128, 512, DYN_SMEMM>>>(b1, b2, 0);

    // mega second half after agg1_h2 completes
    cudaStreamWaitEvent(0, evB, 0);
    k_mega<<<(NN - ROWS_H1 + 127) / 128, 512, DYN_SMEMM>>>(b1, b2, ROWS_H1 / 128);

    k_agg2_lsm<<<(NN + 7) / 8, 256>>>(out);
}